// round 10
// baseline (speedup 1.0000x reference)
#include <cuda_runtime.h>
#include <math.h>
#include <stdint.h>

#define BATCH 2
#define SEQL  2048
#define EMB   1024
#define NH    16
#define HD    64
#define M1    (BATCH*SEQL)   // 4096
#define NQKV  (3*EMB)        // 3072

__device__ float g_qkv[M1 * NQKV];
__device__ float g_q[BATCH*NH*SEQL*HD];   // [B,H,S,D] tf32, pre-scaled
__device__ float g_k[BATCH*NH*SEQL*HD];   // tf32
__device__ float g_v[BATCH*NH*SEQL*HD];   // tf32
__device__ float g_attn[M1 * EMB];        // [B,S,E]

__device__ __forceinline__ float cvt_tf32(float x) {
    uint32_t u;
    asm("cvt.rna.tf32.f32 %0, %1;" : "=r"(u) : "f"(x));
    return __uint_as_float(u);
}
__device__ __forceinline__ float ex2(float x) {
    float y;
    asm("ex2.approx.ftz.f32 %0, %1;" : "=f"(y) : "f"(x));
    return y;
}

__device__ __forceinline__ void mma8(float4& d, const float4& a, float b0, float b1) {
    asm volatile(
        "mma.sync.aligned.m16n8k8.row.col.f32.tf32.tf32.f32 "
        "{%0,%1,%2,%3}, {%4,%5,%6,%7}, {%8,%9}, {%0,%1,%2,%3};"
        : "+f"(d.x), "+f"(d.y), "+f"(d.z), "+f"(d.w)
        : "r"(__float_as_uint(a.x)), "r"(__float_as_uint(a.y)),
          "r"(__float_as_uint(a.z)), "r"(__float_as_uint(a.w)),
          "r"(__float_as_uint(b0)),  "r"(__float_as_uint(b1)));
}

__device__ __forceinline__ int swsl(int slot) { return slot ^ ((slot >> 3) & 3); }

// --- GEMM layouts ---
__device__ __forceinline__ int as_idx(int m, int k) {
    int slot = ((m & 7) << 2) + (k & 3);
    return (((m >> 4) << 1) + (k >> 3)) * 132 + (swsl(slot) << 2)
         + (((k >> 2) & 1) << 1) + ((m >> 3) & 1);
}
__device__ __forceinline__ int bs_idx(int n, int k) {
    int slot = ((n & 7) << 2) + (k & 3);
    return (n >> 3) * 132 + (swsl(slot) << 2)
         + (((k >> 3) & 1) << 1) + ((k >> 2) & 1);
}
// --- Flash layouts ---
__device__ __forceinline__ int kf_idx(int d, int key) {
    int slot = ((key & 7) << 2) + (d & 3);
    return (((key >> 3) << 2) + (d >> 4)) * 132 + (swsl(slot) << 2)
         + (((d >> 3) & 1) << 1) + ((d >> 2) & 1);
}
__device__ __forceinline__ int vf_idx(int key, int d) {
    int slot = ((d & 7) << 2) + (key & 3);
    return (((key >> 4) << 3) + (d >> 3)) * 132 + (swsl(slot) << 2)
         + (((key >> 3) & 1) << 1) + ((key >> 2) & 1);
}
__device__ __forceinline__ int qf_idx(int m, int d) {
    int slot = ((m & 7) << 2) + (d & 3);
    return (d >> 3) * 132 + (swsl(slot) << 2)
         + (((d >> 2) & 1) << 1) + ((m >> 3) & 1);
}
// V row permutation so the P C-fragment is directly an A-fragment.
__device__ __forceinline__ int vperm(int key) {
    int r = key & 7;
    int j = (r & 1) ? (4 + (r >> 1)) : (r >> 1);
    return (key & ~7) | j;
}
__device__ __forceinline__ float4 apfrag(const float4& S) {
    return make_float4(cvt_tf32(S.x), cvt_tf32(S.z), cvt_tf32(S.y), cvt_tf32(S.w));
}

// no-op kernels to shift the ncu capture window onto gemm1 (grid=768)
__global__ void dummy_k() {}

// ---------------------------------------------------------------------------
// Dense GEMM: C[m,n] = sum_k A[m,k]*Bm[n,k], 128x128 tile, BK=16.
// 3-stage DYNAMIC-smem pipeline: LDG chunk kt+2 issued at iter kt, staged at
// iter kt+1, consumed at iter kt+2 -> ~650+ cycles of LDG latency cover.
// Dynamic smem: 3*2112 floats As + 3*2112 floats Bs = 50688 B.
// ---------------------------------------------------------------------------
#define GEMM_SMEM_FLOATS (6 * 2112)
__global__ __launch_bounds__(256, 2) void gemm_tf32(
    const float* __restrict__ A, const float* __restrict__ Bm,
    float* __restrict__ C, int M, int N, int K)
{
    extern __shared__ float gsm[];
    float* AsBase = gsm;             // 3 stages x 2112
    float* BsBase = gsm + 3 * 2112;  // 3 stages x 2112

    const int tid  = threadIdx.x;
    const int lane = tid & 31;
    const int warp = tid >> 5;
    const int wm = warp >> 2;
    const int wn = warp & 3;
    const int m0 = blockIdx.y << 7;
    const int n0 = blockIdx.x << 7;
    const int g = lane >> 2, tig = lane & 3;
    const int sw4 = swsl(lane) << 2;

    const int rA  = tid >> 2;
    const int kkA = (tid & 3) << 2;

    const float* Aptr = A  + (size_t)m0 * K;
    const float* Bptr = Bm + (size_t)n0 * K;

    float4 acc[4][4];
#pragma unroll
    for (int i = 0; i < 4; i++)
#pragma unroll
        for (int j = 0; j < 4; j++) acc[i][j] = make_float4(0.f,0.f,0.f,0.f);

    float4 pa0, pa1, pb0, pb1;
    // chunk 0 -> stage 0
    pa0 = *(const float4*)&Aptr[(size_t)rA * K + kkA];
    pa1 = *(const float4*)&Aptr[(size_t)(rA + 64) * K + kkA];
    pb0 = *(const float4*)&Bptr[(size_t)rA * K + kkA];
    pb1 = *(const float4*)&Bptr[(size_t)(rA + 64) * K + kkA];
#pragma unroll
    for (int u = 0; u < 4; u++) {
        int k = kkA + u;
        AsBase[as_idx(rA,      k)] = cvt_tf32(((const float*)&pa0)[u]);
        AsBase[as_idx(rA + 64, k)] = cvt_tf32(((const float*)&pa1)[u]);
        BsBase[bs_idx(rA,      k)] = cvt_tf32(((const float*)&pb0)[u]);
        BsBase[bs_idx(rA + 64, k)] = cvt_tf32(((const float*)&pb1)[u]);
    }
    // chunk 1 -> regs (staged at iter 0)
    pa0 = *(const float4*)&Aptr[(size_t)rA * K + 16 + kkA];
    pa1 = *(const float4*)&Aptr[(size_t)(rA + 64) * K + 16 + kkA];
    pb0 = *(const float4*)&Bptr[(size_t)rA * K + 16 + kkA];
    pb1 = *(const float4*)&Bptr[(size_t)(rA + 64) * K + 16 + kkA];
    __syncthreads();

    const int NK = K >> 4;
    int stC = 0;                 // compute stage
    for (int kt = 0; kt < NK; kt++) {
        const int stS = (stC == 2) ? 0 : stC + 1;   // store stage = kt+1
        float* AsS = AsBase + stS * 2112;
        float* BsS = BsBase + stS * 2112;
        // stage regs (chunk kt+1)
        if (kt + 1 < NK) {
#pragma unroll
            for (int u = 0; u < 4; u++) {
                int k = kkA + u;
                AsS[as_idx(rA,      k)] = cvt_tf32(((const float*)&pa0)[u]);
                AsS[as_idx(rA + 64, k)] = cvt_tf32(((const float*)&pa1)[u]);
                BsS[bs_idx(rA,      k)] = cvt_tf32(((const float*)&pb0)[u]);
                BsS[bs_idx(rA + 64, k)] = cvt_tf32(((const float*)&pb1)[u]);
            }
        }
        // LDG chunk kt+2 -> regs (consumed at iter kt+1's staging)
        if (kt + 2 < NK) {
            int k0 = (kt + 2) << 4;
            pa0 = *(const float4*)&Aptr[(size_t)rA * K + k0 + kkA];
            pa1 = *(const float4*)&Aptr[(size_t)(rA + 64) * K + k0 + kkA];
            pb0 = *(const float4*)&Bptr[(size_t)rA * K + k0 + kkA];
            pb1 = *(const float4*)&Bptr[(size_t)(rA + 64) * K + k0 + kkA];
        }

        // compute from stage stC
        const float* AsC = AsBase + stC * 2112;
        const float* BsC = BsBase + stC * 2112;
        float4 b4[4];
#pragma unroll
        for (int nt = 0; nt < 4; nt++)
            b4[nt] = *(const float4*)&BsC[(wn * 4 + nt) * 132 + sw4];
#pragma unroll
        for (int k8 = 0; k8 < 2; k8++) {
            float4 a4[4];
#pragma unroll
            for (int mt = 0; mt < 4; mt++)
                a4[mt] = *(const float4*)&AsC[((wm * 4 + mt) * 2 + k8) * 132 + sw4];
#pragma unroll
            for (int mt = 0; mt < 4; mt++)
#pragma unroll
                for (int nt = 0; nt < 4; nt++) {
                    if (k8 == 0) mma8(acc[mt][nt], a4[mt], b4[nt].x, b4[nt].y);
                    else         mma8(acc[mt][nt], a4[mt], b4[nt].z, b4[nt].w);
                }
        }

        stC = stS;
        __syncthreads();
    }

#pragma unroll
    for (int mt = 0; mt < 4; mt++) {
        int mrow = m0 + wm * 64 + mt * 16 + g;
#pragma unroll
        for (int nt = 0; nt < 4; nt++) {
            int ncol = n0 + wn * 32 + nt * 8 + tig * 2;
            *(float2*)&C[(size_t)mrow * N + ncol]       = make_float2(acc[mt][nt].x, acc[mt][nt].y);
            *(float2*)&C[(size_t)(mrow + 8) * N + ncol] = make_float2(acc[mt][nt].z, acc[mt][nt].w);
        }
    }
}

// ---------------------------------------------------------------------------
__global__ __launch_bounds__(256) void split_rope(
    const float* __restrict__ qkv,
    float* __restrict__ q, float* __restrict__ k, float* __restrict__ v)
{
    int idx = blockIdx.x * blockDim.x + threadIdx.x;
    int j = idx & 31;
    int s = (idx >> 5) & (SEQL - 1);
    int h = (idx >> 16) & (NH - 1);
    int b = idx >> 20;

    float inv = expf((float)j * -0.28782313662425575f);
    float fr  = (float)s * inv;
    float sn, c;
    sincosf(fr, &sn, &c);

    size_t row = ((size_t)b * SEQL + s) * NQKV;
    int col = h * HD + j;
    float q1 = qkv[row + col],        q2 = qkv[row + col + 32];
    float k1 = qkv[row + 1024 + col], k2 = qkv[row + 1024 + col + 32];
    float v1 = qkv[row + 2048 + col], v2 = qkv[row + 2048 + col + 32];

    const float QS = 0.18033688011112042f;  // 0.125 * log2(e)
    size_t o = ((size_t)(b * NH + h) * SEQL + s) * HD + j;
    q[o]      = cvt_tf32(QS * (q1 * c - q2 * sn));
    q[o + 32] = cvt_tf32(QS * (q2 * c + q1 * sn));
    k[o]      = cvt_tf32(k1 * c - k2 * sn);
    k[o + 32] = cvt_tf32(k2 * c + k1 * sn);
    v[o]      = cvt_tf32(v1);
    v[o + 32] = cvt_tf32(v2);
}

// ---------------------------------------------------------------------------
// Flash attention, m32 warp tiles (unchanged from R8 — 60% of HMMA ceiling).
// ---------------------------------------------------------------------------
__global__ __launch_bounds__(128, 2) void flash_tf32(
    const float* __restrict__ Qg, const float* __restrict__ Kg,
    const float* __restrict__ Vg, const unsigned char* __restrict__ maskg,
    float* __restrict__ Out)
{
    extern __shared__ float sm[];
    float* Qf = sm;                 // 8 m16-tiles * 1056 = 8448
    float* Kb = sm + 8448;          // 2 x 4224
    float* Vb = sm + 16896;         // 2 x 4224
    float* mk = sm + 25344;         // 2048

    const int tid = threadIdx.x, lane = tid & 31, warp = tid >> 5;
    const int g = lane >> 2, tig = lane & 3;
    const int sw4 = swsl(lane) << 2;
    const int q0 = blockIdx.x << 7;
    const int h  = blockIdx.y;
    const int b  = blockIdx.z;
    const size_t bh = (size_t)(b * NH + h) * SEQL * HD;

    const float* kbase = Kg + bh;
    const float* vbase = Vg + bh;

    {
        const float* qp = Qg + bh + (size_t)q0 * HD;
#pragma unroll
        for (int jj = 0; jj < 16; jj++) {
            int c = tid + jj * 128;
            int row = c >> 4;
            int d4  = (c & 15) << 2;
            float4 qv = *(const float4*)&qp[(size_t)row * HD + d4];
            int w = row >> 4, m = row & 15;
#pragma unroll
            for (int u = 0; u < 4; u++)
                Qf[w * 1056 + qf_idx(m, d4 + u)] = ((const float*)&qv)[u];
        }
#pragma unroll
        for (int jj = 0; jj < 16; jj++) {
            int i = tid + jj * 128;
            mk[i] = maskg[b * SEQL + i] ? -1.0e9f : 0.0f;
        }
    }

    const int cst = tid >> 4;
    const int csd = (tid & 15) << 2;

    {
#pragma unroll
        for (int jj = 0; jj < 8; jj++) {
            int key = cst + jj * 8;
            float4 kv = *(const float4*)&kbase[(size_t)key * HD + csd];
            float4 vv = *(const float4*)&vbase[(size_t)key * HD + csd];
            int pkey = vperm(key);
#pragma unroll
            for (int u = 0; u < 4; u++) {
                Kb[kf_idx(csd + u, key)]  = ((const float*)&kv)[u];
                Vb[vf_idx(pkey, csd + u)] = ((const float*)&vv)[u];
            }
        }
    }
    __syncthreads();

    float4 O[2][8];
#pragma unroll
    for (int mt = 0; mt < 2; mt++)
#pragma unroll
        for (int nt = 0; nt < 8; nt++) O[mt][nt] = make_float4(0.f,0.f,0.f,0.f);
    float l0 = 0.f, l1 = 0.f, l2 = 0.f, l3 = 0.f;

    for (int t = 0; t < SEQL / 64; t++) {
        const int buf = (t & 1) * 4224;
        const bool more = (t + 1 < SEQL / 64);

        float4 pk[8];
        if (more) {
#pragma unroll
            for (int jj = 0; jj < 8; jj++)
                pk[jj] = *(const float4*)&kbase[(size_t)((t+1)*64 + cst + jj*8) * HD + csd];
        }

        float4 S[2][8];
#pragma unroll
        for (int nt = 0; nt < 8; nt++) {
            float2 mv = *(const float2*)&mk[t * 64 + nt * 8 + tig * 2];
            S[0][nt] = make_float4(mv.x, mv.y, mv.x, mv.y);
            S[1][nt] = S[0][nt];
        }

        const float* Kf = Kb + buf;
        const float* Q0 = Qf + (2 * warp)     * 1056;
        const float* Q1 = Qf + (2 * warp + 1) * 1056;
#pragma unroll
        for (int k8p = 0; k8p < 4; k8p++) {
            float4 qa0 = *(const float4*)&Q0[(2 * k8p)     * 132 + sw4];
            float4 qb0 = *(const float4*)&Q0[(2 * k8p + 1) * 132 + sw4];
            float4 qa1 = *(const float4*)&Q1[(2 * k8p)     * 132 + sw4];
            float4 qb1 = *(const float4*)&Q1[(2 * k8p + 1) * 132 + sw4];
#pragma unroll
            for (int ng = 0; ng < 2; ng++) {
                float4 bq[4];
#pragma unroll
                for (int j = 0; j < 4; j++)
                    bq[j] = *(const float4*)&Kf[((ng * 4 + j) * 4 + k8p) * 132 + sw4];
#pragma unroll
                for (int j = 0; j < 4; j++) mma8(S[0][ng*4+j], qa0, bq[j].x, bq[j].y);
#pragma unroll
                for (int j = 0; j < 4; j++) mma8(S[1][ng*4+j], qa1, bq[j].x, bq[j].y);
#pragma unroll
                for (int j = 0; j < 4; j++) mma8(S[0][ng*4+j], qb0, bq[j].z, bq[j].w);
#pragma unroll
                for (int j = 0; j < 4; j++) mma8(S[1][ng*4+j], qb1, bq[j].z, bq[j].w);
            }
        }

        if (more) {
            float* Kn = Kb + (buf ^ 4224);
#pragma unroll
            for (int jj = 0; jj < 8; jj++) {
                int key = cst + jj * 8;
#pragma unroll
                for (int u = 0; u < 4; u++)
                    Kn[kf_idx(csd + u, key)] = ((const float*)&pk[jj])[u];
            }
        }

        float4 pv4[8];
        if (more) {
#pragma unroll
            for (int jj = 0; jj < 8; jj++)
                pv4[jj] = *(const float4*)&vbase[(size_t)((t+1)*64 + cst + jj*8) * HD + csd];
        }

#pragma unroll
        for (int nt = 0; nt < 8; nt++) {
            S[0][nt].x = ex2(S[0][nt].x); S[0][nt].y = ex2(S[0][nt].y);
            S[0][nt].z = ex2(S[0][nt].z); S[0][nt].w = ex2(S[0][nt].w);
            l0 += S[0][nt].x + S[0][nt].y;
            l1 += S[0][nt].z + S[0][nt].w;
            S[1][nt].x = ex2(S[1][nt].x); S[1][nt].y = ex2(S[1][nt].y);
            S[1][nt].z = ex2(S[1][nt].z); S[1][nt].w = ex2(S[1][nt].w);
            l2 += S[1][nt].x + S[1][nt].y;
            l3 += S[1][nt].z + S[1][nt].w;
        }

        const float* Vf = Vb + buf;
#pragma unroll
        for (int kp = 0; kp < 4; kp++) {
            float4 ape0 = apfrag(S[0][2*kp]);
            float4 apo0 = apfrag(S[0][2*kp+1]);
            float4 ape1 = apfrag(S[1][2*kp]);
            float4 apo1 = apfrag(S[1][2*kp+1]);
#pragma unroll
            for (int ng = 0; ng < 2; ng++) {
                float4 bv[4];
#pragma unroll
                for (int j = 0; j < 4; j++)
                    bv[j] = *(const float4*)&Vf[(kp * 8 + ng * 4 + j) * 132 + sw4];
#pragma unroll
                for (int j = 0; j < 4; j++) mma8(O[0][ng*4+j], ape0, bv[j].x, bv[j].y);
#pragma unroll
                for (int j = 0; j < 4; j++) mma8(O[1][ng*4+j], ape1, bv[j].x, bv[j].y);
#pragma unroll
                for (int j = 0; j < 4; j++) mma8(O[0][ng*4+j], apo0, bv[j].z, bv[j].w);
#pragma unroll
                for (int j = 0; j < 4; j++) mma8(O[1][ng*4+j], apo1, bv[j].z, bv[j].w);
            }
        }

        if (more) {
            float* Vn = Vb + (buf ^ 4224);
#pragma unroll
            for (int jj = 0; jj < 8; jj++) {
                int pkey = vperm(cst + jj * 8);
#pragma unroll
                for (int u = 0; u < 4; u++)
                    Vn[vf_idx(pkey, csd + u)] = ((const float*)&pv4[jj])[u];
            }
        }
        __syncthreads();
    }

    l0 += __shfl_xor_sync(0xffffffffu, l0, 1);
    l0 += __shfl_xor_sync(0xffffffffu, l0, 2);
    l1 += __shfl_xor_sync(0xffffffffu, l1, 1);
    l1 += __shfl_xor_sync(0xffffffffu, l1, 2);
    l2 += __shfl_xor_sync(0xffffffffu, l2, 1);
    l2 += __shfl_xor_sync(0xffffffffu, l2, 2);
    l3 += __shfl_xor_sync(0xffffffffu, l3, 1);
    l3 += __shfl_xor_sync(0xffffffffu, l3, 2);
    float inv_[4] = {1.f / l0, 1.f / l1, 1.f / l2, 1.f / l3};
#pragma unroll
    for (int mt = 0; mt < 2; mt++) {
        int s0 = q0 + (2 * warp + mt) * 16 + g;
        float iv0 = inv_[2 * mt], iv1 = inv_[2 * mt + 1];
#pragma unroll
        for (int nt = 0; nt < 8; nt++) {
            int col = h * HD + nt * 8 + tig * 2;
            *(float2*)&Out[(size_t)(b * SEQL + s0) * EMB + col] =
                make_float2(O[mt][nt].x * iv0, O[mt][nt].y * iv0);
            *(float2*)&Out[(size_t)(b * SEQL + s0 + 8) * EMB + col] =
                make_float2(O[mt][nt].z * iv1, O[mt][nt].w * iv1);
        }
    }
}

// ---------------------------------------------------------------------------
extern "C" void kernel_launch(void* const* d_in, const int* in_sizes, int n_in,
                              void* d_out, int out_size)
{
    const float* x            = (const float*)d_in[0];
    const unsigned char* mask = (const unsigned char*)d_in[1];
    const float* Wqkv         = (const float*)d_in[2];
    const float* Wout         = (const float*)d_in[3];
    float* out = (float*)d_out;

    float *qkv, *q, *k, *v, *attn;
    cudaGetSymbolAddress((void**)&qkv,  g_qkv);
    cudaGetSymbolAddress((void**)&q,    g_q);
    cudaGetSymbolAddress((void**)&k,    g_k);
    cudaGetSymbolAddress((void**)&v,    g_v);
    cudaGetSymbolAddress((void**)&attn, g_attn);

    const int FLASH_SMEM = 27392 * 4;               // 109568 B
    const int GEMM_SMEM  = GEMM_SMEM_FLOATS * 4;    // 50688 B
    cudaFuncSetAttribute(flash_tf32,
                         cudaFuncAttributeMaxDynamicSharedMemorySize, FLASH_SMEM);
    cudaFuncSetAttribute(gemm_tf32,
                         cudaFuncAttributeMaxDynamicSharedMemorySize, GEMM_SMEM);

    // keep ncu -s 5 -c 1 window on gemm1 (grid=768)
    dummy_k<<<1, 32>>>();
    dummy_k<<<1, 32>>>();
    dummy_k<<<1, 32>>>();

    dim3 g1(NQKV / 128, M1 / 128);
    gemm_tf32<<<g1, 256, GEMM_SMEM>>>(x, Wqkv, qkv, M1, NQKV, EMB);

    split_rope<<<(BATCH*NH*SEQL*32) / 256, 256>>>(qkv, q, k, v);

    dim3 gf(SEQL / 128, NH, BATCH);
    flash_tf32<<<gf, 128, FLASH_SMEM>>>(q, k, v, mask, attn);

    dim3 g2(EMB / 128, M1 / 128);
    gemm_tf32<<<g2, 256, GEMM_SMEM>>>(attn, Wout, out, M1, EMB, EMB);
}

// round 11
// speedup vs baseline: 1.0804x; 1.0804x over previous
#include <cuda_runtime.h>
#include <math.h>
#include <stdint.h>

#define BATCH 2
#define SEQL  2048
#define EMB   1024
#define NH    16
#define HD    64
#define M1    (BATCH*SEQL)   // 4096
#define NQKV  (3*EMB)        // 3072

__device__ float g_qkv[M1 * NQKV];
__device__ float g_q[BATCH*NH*SEQL*HD];   // [B,H,S,D] tf32, pre-scaled
__device__ float g_k[BATCH*NH*SEQL*HD];   // tf32
__device__ float g_v[BATCH*NH*SEQL*HD];   // tf32
__device__ float g_attn[M1 * EMB];        // [B,S,E]

__device__ __forceinline__ float cvt_tf32(float x) {
    uint32_t u;
    asm("cvt.rna.tf32.f32 %0, %1;" : "=r"(u) : "f"(x));
    return __uint_as_float(u);
}
__device__ __forceinline__ float ex2(float x) {
    float y;
    asm("ex2.approx.ftz.f32 %0, %1;" : "=f"(y) : "f"(x));
    return y;
}

__device__ __forceinline__ void mma8(float4& d, const float4& a, float b0, float b1) {
    asm volatile(
        "mma.sync.aligned.m16n8k8.row.col.f32.tf32.tf32.f32 "
        "{%0,%1,%2,%3}, {%4,%5,%6,%7}, {%8,%9}, {%0,%1,%2,%3};"
        : "+f"(d.x), "+f"(d.y), "+f"(d.z), "+f"(d.w)
        : "r"(__float_as_uint(a.x)), "r"(__float_as_uint(a.y)),
          "r"(__float_as_uint(a.z)), "r"(__float_as_uint(a.w)),
          "r"(__float_as_uint(b0)),  "r"(__float_as_uint(b1)));
}

__device__ __forceinline__ int swsl(int slot) { return slot ^ ((slot >> 3) & 3); }

// --- GEMM layouts (tile stride 132, swizzled slots) ---
__device__ __forceinline__ int as_idx(int m, int k) {
    int slot = ((m & 7) << 2) + (k & 3);
    return (((m >> 4) << 1) + (k >> 3)) * 132 + (swsl(slot) << 2)
         + (((k >> 2) & 1) << 1) + ((m >> 3) & 1);
}
__device__ __forceinline__ int bs_idx(int n, int k) {
    int slot = ((n & 7) << 2) + (k & 3);
    return (n >> 3) * 132 + (swsl(slot) << 2)
         + (((k >> 3) & 1) << 1) + ((k >> 2) & 1);
}
// --- Flash layouts ---
__device__ __forceinline__ int kf_idx(int d, int key) {
    int slot = ((key & 7) << 2) + (d & 3);
    return (((key >> 3) << 2) + (d >> 4)) * 132 + (swsl(slot) << 2)
         + (((d >> 3) & 1) << 1) + ((d >> 2) & 1);
}
__device__ __forceinline__ int vf_idx(int key, int d) {
    int slot = ((d & 7) << 2) + (key & 3);
    return (((key >> 4) << 3) + (d >> 3)) * 132 + (swsl(slot) << 2)
         + (((key >> 3) & 1) << 1) + ((key >> 2) & 1);
}
__device__ __forceinline__ int qf_idx(int m, int d) {
    int slot = ((m & 7) << 2) + (d & 3);
    return (d >> 3) * 132 + (swsl(slot) << 2)
         + (((d >> 2) & 1) << 1) + ((m >> 3) & 1);
}
// V row permutation so the P C-fragment is directly an A-fragment.
__device__ __forceinline__ int vperm(int key) {
    int r = key & 7;
    int j = (r & 1) ? (4 + (r >> 1)) : (r >> 1);
    return (key & ~7) | j;
}
__device__ __forceinline__ float4 apfrag(const float4& S) {
    return make_float4(cvt_tf32(S.x), cvt_tf32(S.z), cvt_tf32(S.y), cvt_tf32(S.w));
}

// no-op kernels to keep the ncu capture window on gemm1 (grid=768)
__global__ void dummy_k() {}

// ---------------------------------------------------------------------------
// Dense GEMM: C[m,n] = sum_k A[m,k]*Bm[n,k], 128x128 block tile, BK=16.
// 128 threads, 4 warps, warp tile 64x64 (flash-style): 64 HMMA per warp per
// iter over 32 independent acc tiles; 2-stage double buffer; 2 CTAs/SM.
// ---------------------------------------------------------------------------
__global__ __launch_bounds__(128, 2) void gemm_tf32(
    const float* __restrict__ A, const float* __restrict__ Bm,
    float* __restrict__ C, int M, int N, int K)
{
    __shared__ float As[2][2112];
    __shared__ float Bs[2][2112];

    const int tid  = threadIdx.x;
    const int lane = tid & 31;
    const int warp = tid >> 5;      // 0..3
    const int wm = warp >> 1;       // 0..1 -> m offset wm*64
    const int wn = warp & 1;        // 0..1 -> n offset wn*64
    const int m0 = blockIdx.y << 7;
    const int n0 = blockIdx.x << 7;
    const int g = lane >> 2, tig = lane & 3;
    const int sw4 = swsl(lane) << 2;

    const int rA  = tid >> 2;          // 0..31 (row base; rows rA+32*blk)
    const int kkA = (tid & 3) << 2;    // 0,4,8,12

    const float* Aptr = A  + (size_t)m0 * K;
    const float* Bptr = Bm + (size_t)n0 * K;

    float4 acc[4][8];
#pragma unroll
    for (int i = 0; i < 4; i++)
#pragma unroll
        for (int j = 0; j < 8; j++) acc[i][j] = make_float4(0.f,0.f,0.f,0.f);

    float4 pa[4], pb[4];
    // chunk 0 -> stage 0
#pragma unroll
    for (int blk = 0; blk < 4; blk++) {
        pa[blk] = *(const float4*)&Aptr[(size_t)(rA + 32*blk) * K + kkA];
        pb[blk] = *(const float4*)&Bptr[(size_t)(rA + 32*blk) * K + kkA];
    }
#pragma unroll
    for (int blk = 0; blk < 4; blk++)
#pragma unroll
        for (int u = 0; u < 4; u++) {
            int k = kkA + u;
            As[0][as_idx(rA + 32*blk, k)] = cvt_tf32(((const float*)&pa[blk])[u]);
            Bs[0][bs_idx(rA + 32*blk, k)] = cvt_tf32(((const float*)&pb[blk])[u]);
        }
    __syncthreads();

    const int NK = K >> 4;
    for (int kt = 0; kt < NK; kt++) {
        const int st = kt & 1;
        if (kt + 1 < NK) {
            int k0 = (kt + 1) << 4;
#pragma unroll
            for (int blk = 0; blk < 4; blk++) {
                pa[blk] = *(const float4*)&Aptr[(size_t)(rA + 32*blk) * K + k0 + kkA];
                pb[blk] = *(const float4*)&Bptr[(size_t)(rA + 32*blk) * K + k0 + kkA];
            }
        }

        // compute: warp tile 64x64, b-frags shared across k8 halves
#pragma unroll
        for (int ng = 0; ng < 2; ng++) {
            float4 b4[4];
#pragma unroll
            for (int j = 0; j < 4; j++)
                b4[j] = *(const float4*)&Bs[st][(wn * 8 + ng * 4 + j) * 132 + sw4];
#pragma unroll
            for (int k8 = 0; k8 < 2; k8++) {
                float4 a4[4];
#pragma unroll
                for (int mt = 0; mt < 4; mt++)
                    a4[mt] = *(const float4*)&As[st][((wm * 4 + mt) * 2 + k8) * 132 + sw4];
#pragma unroll
                for (int mt = 0; mt < 4; mt++)
#pragma unroll
                    for (int j = 0; j < 4; j++) {
                        if (k8 == 0) mma8(acc[mt][ng*4+j], a4[mt], b4[j].x, b4[j].y);
                        else         mma8(acc[mt][ng*4+j], a4[mt], b4[j].z, b4[j].w);
                    }
            }
        }

        // stage chunk kt+1
        if (kt + 1 < NK) {
            const int s2 = (kt + 1) & 1;
#pragma unroll
            for (int blk = 0; blk < 4; blk++)
#pragma unroll
                for (int u = 0; u < 4; u++) {
                    int k = kkA + u;
                    As[s2][as_idx(rA + 32*blk, k)] = cvt_tf32(((const float*)&pa[blk])[u]);
                    Bs[s2][bs_idx(rA + 32*blk, k)] = cvt_tf32(((const float*)&pb[blk])[u]);
                }
        }
        __syncthreads();
    }

#pragma unroll
    for (int mt = 0; mt < 4; mt++) {
        int mrow = m0 + wm * 64 + mt * 16 + g;
#pragma unroll
        for (int nt = 0; nt < 8; nt++) {
            int ncol = n0 + wn * 64 + nt * 8 + tig * 2;
            *(float2*)&C[(size_t)mrow * N + ncol]       = make_float2(acc[mt][nt].x, acc[mt][nt].y);
            *(float2*)&C[(size_t)(mrow + 8) * N + ncol] = make_float2(acc[mt][nt].z, acc[mt][nt].w);
        }
    }
}

// ---------------------------------------------------------------------------
__global__ __launch_bounds__(256) void split_rope(
    const float* __restrict__ qkv,
    float* __restrict__ q, float* __restrict__ k, float* __restrict__ v)
{
    int idx = blockIdx.x * blockDim.x + threadIdx.x;
    int j = idx & 31;
    int s = (idx >> 5) & (SEQL - 1);
    int h = (idx >> 16) & (NH - 1);
    int b = idx >> 20;

    float inv = expf((float)j * -0.28782313662425575f);
    float fr  = (float)s * inv;
    float sn, c;
    sincosf(fr, &sn, &c);

    size_t row = ((size_t)b * SEQL + s) * NQKV;
    int col = h * HD + j;
    float q1 = qkv[row + col],        q2 = qkv[row + col + 32];
    float k1 = qkv[row + 1024 + col], k2 = qkv[row + 1024 + col + 32];
    float v1 = qkv[row + 2048 + col], v2 = qkv[row + 2048 + col + 32];

    const float QS = 0.18033688011112042f;  // 0.125 * log2(e)
    size_t o = ((size_t)(b * NH + h) * SEQL + s) * HD + j;
    q[o]      = cvt_tf32(QS * (q1 * c - q2 * sn));
    q[o + 32] = cvt_tf32(QS * (q2 * c + q1 * sn));
    k[o]      = cvt_tf32(k1 * c - k2 * sn);
    k[o + 32] = cvt_tf32(k2 * c + k1 * sn);
    v[o]      = cvt_tf32(v1);
    v[o + 32] = cvt_tf32(v2);
}

// ---------------------------------------------------------------------------
// Flash attention, m32 warp tiles (unchanged — 60% of HMMA ceiling).
// ---------------------------------------------------------------------------
__global__ __launch_bounds__(128, 2) void flash_tf32(
    const float* __restrict__ Qg, const float* __restrict__ Kg,
    const float* __restrict__ Vg, const unsigned char* __restrict__ maskg,
    float* __restrict__ Out)
{
    extern __shared__ float sm[];
    float* Qf = sm;                 // 8 m16-tiles * 1056 = 8448
    float* Kb = sm + 8448;          // 2 x 4224
    float* Vb = sm + 16896;         // 2 x 4224
    float* mk = sm + 25344;         // 2048

    const int tid = threadIdx.x, lane = tid & 31, warp = tid >> 5;
    const int g = lane >> 2, tig = lane & 3;
    const int sw4 = swsl(lane) << 2;
    const int q0 = blockIdx.x << 7;
    const int h  = blockIdx.y;
    const int b  = blockIdx.z;
    const size_t bh = (size_t)(b * NH + h) * SEQL * HD;

    const float* kbase = Kg + bh;
    const float* vbase = Vg + bh;

    {
        const float* qp = Qg + bh + (size_t)q0 * HD;
#pragma unroll
        for (int jj = 0; jj < 16; jj++) {
            int c = tid + jj * 128;
            int row = c >> 4;
            int d4  = (c & 15) << 2;
            float4 qv = *(const float4*)&qp[(size_t)row * HD + d4];
            int w = row >> 4, m = row & 15;
#pragma unroll
            for (int u = 0; u < 4; u++)
                Qf[w * 1056 + qf_idx(m, d4 + u)] = ((const float*)&qv)[u];
        }
#pragma unroll
        for (int jj = 0; jj < 16; jj++) {
            int i = tid + jj * 128;
            mk[i] = maskg[b * SEQL + i] ? -1.0e9f : 0.0f;
        }
    }

    const int cst = tid >> 4;
    const int csd = (tid & 15) << 2;

    {
#pragma unroll
        for (int jj = 0; jj < 8; jj++) {
            int key = cst + jj * 8;
            float4 kv = *(const float4*)&kbase[(size_t)key * HD + csd];
            float4 vv = *(const float4*)&vbase[(size_t)key * HD + csd];
            int pkey = vperm(key);
#pragma unroll
            for (int u = 0; u < 4; u++) {
                Kb[kf_idx(csd + u, key)]  = ((const float*)&kv)[u];
                Vb[vf_idx(pkey, csd + u)] = ((const float*)&vv)[u];
            }
        }
    }
    __syncthreads();

    float4 O[2][8];
#pragma unroll
    for (int mt = 0; mt < 2; mt++)
#pragma unroll
        for (int nt = 0; nt < 8; nt++) O[mt][nt] = make_float4(0.f,0.f,0.f,0.f);
    float l0 = 0.f, l1 = 0.f, l2 = 0.f, l3 = 0.f;

    for (int t = 0; t < SEQL / 64; t++) {
        const int buf = (t & 1) * 4224;
        const bool more = (t + 1 < SEQL / 64);

        float4 pk[8];
        if (more) {
#pragma unroll
            for (int jj = 0; jj < 8; jj++)
                pk[jj] = *(const float4*)&kbase[(size_t)((t+1)*64 + cst + jj*8) * HD + csd];
        }

        float4 S[2][8];
#pragma unroll
        for (int nt = 0; nt < 8; nt++) {
            float2 mv = *(const float2*)&mk[t * 64 + nt * 8 + tig * 2];
            S[0][nt] = make_float4(mv.x, mv.y, mv.x, mv.y);
            S[1][nt] = S[0][nt];
        }

        const float* Kf = Kb + buf;
        const float* Q0 = Qf + (2 * warp)     * 1056;
        const float* Q1 = Qf + (2 * warp + 1) * 1056;
#pragma unroll
        for (int k8p = 0; k8p < 4; k8p++) {
            float4 qa0 = *(const float4*)&Q0[(2 * k8p)     * 132 + sw4];
            float4 qb0 = *(const float4*)&Q0[(2 * k8p + 1) * 132 + sw4];
            float4 qa1 = *(const float4*)&Q1[(2 * k8p)     * 132 + sw4];
            float4 qb1 = *(const float4*)&Q1[(2 * k8p + 1) * 132 + sw4];
#pragma unroll
            for (int ng = 0; ng < 2; ng++) {
                float4 bq[4];
#pragma unroll
                for (int j = 0; j < 4; j++)
                    bq[j] = *(const float4*)&Kf[((ng * 4 + j) * 4 + k8p) * 132 + sw4];
#pragma unroll
                for (int j = 0; j < 4; j++) mma8(S[0][ng*4+j], qa0, bq[j].x, bq[j].y);
#pragma unroll
                for (int j = 0; j < 4; j++) mma8(S[1][ng*4+j], qa1, bq[j].x, bq[j].y);
#pragma unroll
                for (int j = 0; j < 4; j++) mma8(S[0][ng*4+j], qb0, bq[j].z, bq[j].w);
#pragma unroll
                for (int j = 0; j < 4; j++) mma8(S[1][ng*4+j], qb1, bq[j].z, bq[j].w);
            }
        }

        if (more) {
            float* Kn = Kb + (buf ^ 4224);
#pragma unroll
            for (int jj = 0; jj < 8; jj++) {
                int key = cst + jj * 8;
#pragma unroll
                for (int u = 0; u < 4; u++)
                    Kn[kf_idx(csd + u, key)] = ((const float*)&pk[jj])[u];
            }
        }

        float4 pv4[8];
        if (more) {
#pragma unroll
            for (int jj = 0; jj < 8; jj++)
                pv4[jj] = *(const float4*)&vbase[(size_t)((t+1)*64 + cst + jj*8) * HD + csd];
        }

#pragma unroll
        for (int nt = 0; nt < 8; nt++) {
            S[0][nt].x = ex2(S[0][nt].x); S[0][nt].y = ex2(S[0][nt].y);
            S[0][nt].z = ex2(S[0][nt].z); S[0][nt].w = ex2(S[0][nt].w);
            l0 += S[0][nt].x + S[0][nt].y;
            l1 += S[0][nt].z + S[0][nt].w;
            S[1][nt].x = ex2(S[1][nt].x); S[1][nt].y = ex2(S[1][nt].y);
            S[1][nt].z = ex2(S[1][nt].z); S[1][nt].w = ex2(S[1][nt].w);
            l2 += S[1][nt].x + S[1][nt].y;
            l3 += S[1][nt].z + S[1][nt].w;
        }

        const float* Vf = Vb + buf;
#pragma unroll
        for (int kp = 0; kp < 4; kp++) {
            float4 ape0 = apfrag(S[0][2*kp]);
            float4 apo0 = apfrag(S[0][2*kp+1]);
            float4 ape1 = apfrag(S[1][2*kp]);
            float4 apo1 = apfrag(S[1][2*kp+1]);
#pragma unroll
            for (int ng = 0; ng < 2; ng++) {
                float4 bv[4];
#pragma unroll
                for (int j = 0; j < 4; j++)
                    bv[j] = *(const float4*)&Vf[(kp * 8 + ng * 4 + j) * 132 + sw4];
#pragma unroll
                for (int j = 0; j < 4; j++) mma8(O[0][ng*4+j], ape0, bv[j].x, bv[j].y);
#pragma unroll
                for (int j = 0; j < 4; j++) mma8(O[1][ng*4+j], ape1, bv[j].x, bv[j].y);
#pragma unroll
                for (int j = 0; j < 4; j++) mma8(O[0][ng*4+j], apo0, bv[j].z, bv[j].w);
#pragma unroll
                for (int j = 0; j < 4; j++) mma8(O[1][ng*4+j], apo1, bv[j].z, bv[j].w);
            }
        }

        if (more) {
            float* Vn = Vb + (buf ^ 4224);
#pragma unroll
            for (int jj = 0; jj < 8; jj++) {
                int pkey = vperm(cst + jj * 8);
#pragma unroll
                for (int u = 0; u < 4; u++)
                    Vn[vf_idx(pkey, csd + u)] = ((const float*)&pv4[jj])[u];
            }
        }
        __syncthreads();
    }

    l0 += __shfl_xor_sync(0xffffffffu, l0, 1);
    l0 += __shfl_xor_sync(0xffffffffu, l0, 2);
    l1 += __shfl_xor_sync(0xffffffffu, l1, 1);
    l1 += __shfl_xor_sync(0xffffffffu, l1, 2);
    l2 += __shfl_xor_sync(0xffffffffu, l2, 1);
    l2 += __shfl_xor_sync(0xffffffffu, l2, 2);
    l3 += __shfl_xor_sync(0xffffffffu, l3, 1);
    l3 += __shfl_xor_sync(0xffffffffu, l3, 2);
    float inv_[4] = {1.f / l0, 1.f / l1, 1.f / l2, 1.f / l3};
#pragma unroll
    for (int mt = 0; mt < 2; mt++) {
        int s0 = q0 + (2 * warp + mt) * 16 + g;
        float iv0 = inv_[2 * mt], iv1 = inv_[2 * mt + 1];
#pragma unroll
        for (int nt = 0; nt < 8; nt++) {
            int col = h * HD + nt * 8 + tig * 2;
            *(float2*)&Out[(size_t)(b * SEQL + s0) * EMB + col] =
                make_float2(O[mt][nt].x * iv0, O[mt][nt].y * iv0);
            *(float2*)&Out[(size_t)(b * SEQL + s0 + 8) * EMB + col] =
                make_float2(O[mt][nt].z * iv1, O[mt][nt].w * iv1);
        }
    }
}

// ---------------------------------------------------------------------------
extern "C" void kernel_launch(void* const* d_in, const int* in_sizes, int n_in,
                              void* d_out, int out_size)
{
    const float* x            = (const float*)d_in[0];
    const unsigned char* mask = (const unsigned char*)d_in[1];
    const float* Wqkv         = (const float*)d_in[2];
    const float* Wout         = (const float*)d_in[3];
    float* out = (float*)d_out;

    float *qkv, *q, *k, *v, *attn;
    cudaGetSymbolAddress((void**)&qkv,  g_qkv);
    cudaGetSymbolAddress((void**)&q,    g_q);
    cudaGetSymbolAddress((void**)&k,    g_k);
    cudaGetSymbolAddress((void**)&v,    g_v);
    cudaGetSymbolAddress((void**)&attn, g_attn);

    const int FLASH_SMEM = 27392 * 4;   // 109568 B
    cudaFuncSetAttribute(flash_tf32,
                         cudaFuncAttributeMaxDynamicSharedMemorySize, FLASH_SMEM);

    // keep ncu -s 5 -c 1 window on gemm1 (grid=768)
    dummy_k<<<1, 32>>>();
    dummy_k<<<1, 32>>>();
    dummy_k<<<1, 32>>>();

    dim3 g1(NQKV / 128, M1 / 128);
    gemm_tf32<<<g1, 128>>>(x, Wqkv, qkv, M1, NQKV, EMB);

    split_rope<<<(BATCH*NH*SEQL*32) / 256, 256>>>(qkv, q, k, v);

    dim3 gf(SEQL / 128, NH, BATCH);
    flash_tf32<<<gf, 128, FLASH_SMEM>>>(q, k, v, mask, attn);

    dim3 g2(EMB / 128, M1 / 128);
    gemm_tf32<<<g2, 128>>>(attn, Wout, out, M1, EMB, EMB);
}

// round 12
// speedup vs baseline: 1.1108x; 1.0282x over previous
#include <cuda_runtime.h>
#include <math.h>
#include <stdint.h>

#define BATCH 2
#define SEQL  2048
#define EMB   1024
#define NH    16
#define HD    64
#define M1    (BATCH*SEQL)   // 4096
#define NQKV  (3*EMB)        // 3072

__device__ float g_qkv[M1 * NQKV];
__device__ float g_q[BATCH*NH*SEQL*HD];   // [B,H,S,D] tf32, pre-scaled
__device__ float g_k[BATCH*NH*SEQL*HD];   // tf32
__device__ float g_v[BATCH*NH*SEQL*HD];   // tf32
__device__ float g_attn[M1 * EMB];        // [B,S,E]

__device__ __forceinline__ float cvt_tf32(float x) {
    uint32_t u;
    asm("cvt.rna.tf32.f32 %0, %1;" : "=r"(u) : "f"(x));
    return __uint_as_float(u);
}
__device__ __forceinline__ float ex2(float x) {
    float y;
    asm("ex2.approx.ftz.f32 %0, %1;" : "=f"(y) : "f"(x));
    return y;
}

__device__ __forceinline__ void mma8(float4& d, const float4& a, float b0, float b1) {
    asm volatile(
        "mma.sync.aligned.m16n8k8.row.col.f32.tf32.tf32.f32 "
        "{%0,%1,%2,%3}, {%4,%5,%6,%7}, {%8,%9}, {%0,%1,%2,%3};"
        : "+f"(d.x), "+f"(d.y), "+f"(d.z), "+f"(d.w)
        : "r"(__float_as_uint(a.x)), "r"(__float_as_uint(a.y)),
          "r"(__float_as_uint(a.z)), "r"(__float_as_uint(a.w)),
          "r"(__float_as_uint(b0)),  "r"(__float_as_uint(b1)));
}

__device__ __forceinline__ int swsl(int slot) { return slot ^ ((slot >> 3) & 3); }

// --- GEMM layouts (tile stride 132, swizzled slots) ---
__device__ __forceinline__ int as_idx(int m, int k) {
    int slot = ((m & 7) << 2) + (k & 3);
    return (((m >> 4) << 1) + (k >> 3)) * 132 + (swsl(slot) << 2)
         + (((k >> 2) & 1) << 1) + ((m >> 3) & 1);
}
__device__ __forceinline__ int bs_idx(int n, int k) {
    int slot = ((n & 7) << 2) + (k & 3);
    return (n >> 3) * 132 + (swsl(slot) << 2)
         + (((k >> 3) & 1) << 1) + ((k >> 2) & 1);
}
// --- Flash layouts ---
__device__ __forceinline__ int kf_idx(int d, int key) {
    int slot = ((key & 7) << 2) + (d & 3);
    return (((key >> 3) << 2) + (d >> 4)) * 132 + (swsl(slot) << 2)
         + (((d >> 3) & 1) << 1) + ((d >> 2) & 1);
}
__device__ __forceinline__ int vf_idx(int key, int d) {
    int slot = ((d & 7) << 2) + (key & 3);
    return (((key >> 4) << 3) + (d >> 3)) * 132 + (swsl(slot) << 2)
         + (((key >> 3) & 1) << 1) + ((key >> 2) & 1);
}
__device__ __forceinline__ int qf_idx(int m, int d) {
    int slot = ((m & 7) << 2) + (d & 3);
    return (d >> 3) * 132 + (swsl(slot) << 2)
         + (((d >> 2) & 1) << 1) + ((m >> 3) & 1);
}
// V row permutation so the P C-fragment is directly an A-fragment.
__device__ __forceinline__ int vperm(int key) {
    int r = key & 7;
    int j = (r & 1) ? (4 + (r >> 1)) : (r >> 1);
    return (key & ~7) | j;
}
__device__ __forceinline__ float4 apfrag(const float4& S) {
    return make_float4(cvt_tf32(S.x), cvt_tf32(S.z), cvt_tf32(S.y), cvt_tf32(S.w));
}

// no-op kernels to keep the ncu capture window on gemm1 (grid=768)
__global__ void dummy_k() {}

// ---------------------------------------------------------------------------
// Dense GEMM: 128x128 block tile, BK=16, 4 warps x (64x64), 2 CTAs/SM.
// Staging addresses are affine: addr = {a,b}off[u] + blk*528, precomputed
// once -> scatter STS becomes [Ru + imm], killing the per-iter index ALU.
// ---------------------------------------------------------------------------
__global__ __launch_bounds__(128, 2) void gemm_tf32(
    const float* __restrict__ A, const float* __restrict__ Bm,
    float* __restrict__ C, int M, int N, int K)
{
    __shared__ float As[2][2112];
    __shared__ float Bs[2][2112];

    const int tid  = threadIdx.x;
    const int lane = tid & 31;
    const int warp = tid >> 5;      // 0..3
    const int wm = warp >> 1;       // 0..1 -> m offset wm*64
    const int wn = warp & 1;        // 0..1 -> n offset wn*64
    const int m0 = blockIdx.y << 7;
    const int n0 = blockIdx.x << 7;
    const int g = lane >> 2, tig = lane & 3;
    const int sw4 = swsl(lane) << 2;

    const int rA  = tid >> 2;          // 0..31
    const int kkA = (tid & 3) << 2;    // 0,4,8,12

    // precomputed staging offsets (blk stride 528 for both A and B)
    int aoff[4], boff[4];
#pragma unroll
    for (int u = 0; u < 4; u++) {
        aoff[u] = as_idx(rA, kkA + u);
        boff[u] = bs_idx(rA, kkA + u);
    }

    const float* Aptr = A  + (size_t)m0 * K;
    const float* Bptr = Bm + (size_t)n0 * K;

    float4 acc[4][8];
#pragma unroll
    for (int i = 0; i < 4; i++)
#pragma unroll
        for (int j = 0; j < 8; j++) acc[i][j] = make_float4(0.f,0.f,0.f,0.f);

    float4 pa[4], pb[4];
    // chunk 0 -> stage 0
#pragma unroll
    for (int blk = 0; blk < 4; blk++) {
        pa[blk] = *(const float4*)&Aptr[(size_t)(rA + 32*blk) * K + kkA];
        pb[blk] = *(const float4*)&Bptr[(size_t)(rA + 32*blk) * K + kkA];
    }
#pragma unroll
    for (int blk = 0; blk < 4; blk++)
#pragma unroll
        for (int u = 0; u < 4; u++) {
            As[0][aoff[u] + blk * 528] = cvt_tf32(((const float*)&pa[blk])[u]);
            Bs[0][boff[u] + blk * 528] = cvt_tf32(((const float*)&pb[blk])[u]);
        }
    __syncthreads();

    const int NK = K >> 4;
    for (int kt = 0; kt < NK; kt++) {
        const int st = kt & 1;
        if (kt + 1 < NK) {
            int k0 = (kt + 1) << 4;
#pragma unroll
            for (int blk = 0; blk < 4; blk++) {
                pa[blk] = *(const float4*)&Aptr[(size_t)(rA + 32*blk) * K + k0 + kkA];
                pb[blk] = *(const float4*)&Bptr[(size_t)(rA + 32*blk) * K + k0 + kkA];
            }
        }

        // compute: warp tile 64x64
#pragma unroll
        for (int ng = 0; ng < 2; ng++) {
            float4 b4[4];
#pragma unroll
            for (int j = 0; j < 4; j++)
                b4[j] = *(const float4*)&Bs[st][(wn * 8 + ng * 4 + j) * 132 + sw4];
#pragma unroll
            for (int k8 = 0; k8 < 2; k8++) {
                float4 a4[4];
#pragma unroll
                for (int mt = 0; mt < 4; mt++)
                    a4[mt] = *(const float4*)&As[st][((wm * 4 + mt) * 2 + k8) * 132 + sw4];
#pragma unroll
                for (int mt = 0; mt < 4; mt++)
#pragma unroll
                    for (int j = 0; j < 4; j++) {
                        if (k8 == 0) mma8(acc[mt][ng*4+j], a4[mt], b4[j].x, b4[j].y);
                        else         mma8(acc[mt][ng*4+j], a4[mt], b4[j].z, b4[j].w);
                    }
            }
        }

        // stage chunk kt+1 (precomputed addresses + immediates)
        if (kt + 1 < NK) {
            const int s2 = (kt + 1) & 1;
#pragma unroll
            for (int blk = 0; blk < 4; blk++)
#pragma unroll
                for (int u = 0; u < 4; u++) {
                    As[s2][aoff[u] + blk * 528] = cvt_tf32(((const float*)&pa[blk])[u]);
                    Bs[s2][boff[u] + blk * 528] = cvt_tf32(((const float*)&pb[blk])[u]);
                }
        }
        __syncthreads();
    }

#pragma unroll
    for (int mt = 0; mt < 4; mt++) {
        int mrow = m0 + wm * 64 + mt * 16 + g;
#pragma unroll
        for (int nt = 0; nt < 8; nt++) {
            int ncol = n0 + wn * 64 + nt * 8 + tig * 2;
            *(float2*)&C[(size_t)mrow * N + ncol]       = make_float2(acc[mt][nt].x, acc[mt][nt].y);
            *(float2*)&C[(size_t)(mrow + 8) * N + ncol] = make_float2(acc[mt][nt].z, acc[mt][nt].w);
        }
    }
}

// ---------------------------------------------------------------------------
__global__ __launch_bounds__(256) void split_rope(
    const float* __restrict__ qkv,
    float* __restrict__ q, float* __restrict__ k, float* __restrict__ v)
{
    int idx = blockIdx.x * blockDim.x + threadIdx.x;
    int j = idx & 31;
    int s = (idx >> 5) & (SEQL - 1);
    int h = (idx >> 16) & (NH - 1);
    int b = idx >> 20;

    float inv = expf((float)j * -0.28782313662425575f);
    float fr  = (float)s * inv;
    float sn, c;
    sincosf(fr, &sn, &c);

    size_t row = ((size_t)b * SEQL + s) * NQKV;
    int col = h * HD + j;
    float q1 = qkv[row + col],        q2 = qkv[row + col + 32];
    float k1 = qkv[row + 1024 + col], k2 = qkv[row + 1024 + col + 32];
    float v1 = qkv[row + 2048 + col], v2 = qkv[row + 2048 + col + 32];

    const float QS = 0.18033688011112042f;  // 0.125 * log2(e)
    size_t o = ((size_t)(b * NH + h) * SEQL + s) * HD + j;
    q[o]      = cvt_tf32(QS * (q1 * c - q2 * sn));
    q[o + 32] = cvt_tf32(QS * (q2 * c + q1 * sn));
    k[o]      = cvt_tf32(k1 * c - k2 * sn);
    k[o + 32] = cvt_tf32(k2 * c + k1 * sn);
    v[o]      = cvt_tf32(v1);
    v[o + 32] = cvt_tf32(v2);
}

// ---------------------------------------------------------------------------
// Flash attention, m32 warp tiles. KV staging addresses precomputed:
// kf = koff[u] + jj*528; vf = voff[u] + (jj>>1)*1056 + (jj&1)*2.
// ---------------------------------------------------------------------------
__global__ __launch_bounds__(128, 2) void flash_tf32(
    const float* __restrict__ Qg, const float* __restrict__ Kg,
    const float* __restrict__ Vg, const unsigned char* __restrict__ maskg,
    float* __restrict__ Out)
{
    extern __shared__ float sm[];
    float* Qf = sm;                 // 8 m16-tiles * 1056 = 8448
    float* Kb = sm + 8448;          // 2 x 4224
    float* Vb = sm + 16896;         // 2 x 4224
    float* mk = sm + 25344;         // 2048

    const int tid = threadIdx.x, lane = tid & 31, warp = tid >> 5;
    const int g = lane >> 2, tig = lane & 3;
    const int sw4 = swsl(lane) << 2;
    const int q0 = blockIdx.x << 7;
    const int h  = blockIdx.y;
    const int b  = blockIdx.z;
    const size_t bh = (size_t)(b * NH + h) * SEQL * HD;

    const float* kbase = Kg + bh;
    const float* vbase = Vg + bh;

    const int cst = tid >> 4;           // 0..7
    const int csd = (tid & 15) << 2;

    // precomputed staging offsets
    int koff[4], voff[4];
#pragma unroll
    for (int u = 0; u < 4; u++) {
        koff[u] = kf_idx(csd + u, cst);
        voff[u] = vf_idx(vperm(cst), csd + u);
    }

    {
        const float* qp = Qg + bh + (size_t)q0 * HD;
#pragma unroll
        for (int jj = 0; jj < 16; jj++) {
            int c = tid + jj * 128;
            int row = c >> 4;
            int d4  = (c & 15) << 2;
            float4 qv = *(const float4*)&qp[(size_t)row * HD + d4];
            int w = row >> 4, m = row & 15;
#pragma unroll
            for (int u = 0; u < 4; u++)
                Qf[w * 1056 + qf_idx(m, d4 + u)] = ((const float*)&qv)[u];
        }
#pragma unroll
        for (int jj = 0; jj < 16; jj++) {
            int i = tid + jj * 128;
            mk[i] = maskg[b * SEQL + i] ? -1.0e9f : 0.0f;
        }
    }

    // prologue: KV tile 0
    {
#pragma unroll
        for (int jj = 0; jj < 8; jj++) {
            int key = cst + jj * 8;
            float4 kv = *(const float4*)&kbase[(size_t)key * HD + csd];
            float4 vv = *(const float4*)&vbase[(size_t)key * HD + csd];
#pragma unroll
            for (int u = 0; u < 4; u++) {
                Kb[koff[u] + jj * 528] = ((const float*)&kv)[u];
                Vb[voff[u] + (jj >> 1) * 1056 + (jj & 1) * 2] = ((const float*)&vv)[u];
            }
        }
    }
    __syncthreads();

    float4 O[2][8];
#pragma unroll
    for (int mt = 0; mt < 2; mt++)
#pragma unroll
        for (int nt = 0; nt < 8; nt++) O[mt][nt] = make_float4(0.f,0.f,0.f,0.f);
    float l0 = 0.f, l1 = 0.f, l2 = 0.f, l3 = 0.f;

    for (int t = 0; t < SEQL / 64; t++) {
        const int buf = (t & 1) * 4224;
        const bool more = (t + 1 < SEQL / 64);

        float4 pk[8];
        if (more) {
#pragma unroll
            for (int jj = 0; jj < 8; jj++)
                pk[jj] = *(const float4*)&kbase[(size_t)((t+1)*64 + cst + jj*8) * HD + csd];
        }

        float4 S[2][8];
#pragma unroll
        for (int nt = 0; nt < 8; nt++) {
            float2 mv = *(const float2*)&mk[t * 64 + nt * 8 + tig * 2];
            S[0][nt] = make_float4(mv.x, mv.y, mv.x, mv.y);
            S[1][nt] = S[0][nt];
        }

        const float* Kf = Kb + buf;
        const float* Q0 = Qf + (2 * warp)     * 1056;
        const float* Q1 = Qf + (2 * warp + 1) * 1056;
#pragma unroll
        for (int k8p = 0; k8p < 4; k8p++) {
            float4 qa0 = *(const float4*)&Q0[(2 * k8p)     * 132 + sw4];
            float4 qb0 = *(const float4*)&Q0[(2 * k8p + 1) * 132 + sw4];
            float4 qa1 = *(const float4*)&Q1[(2 * k8p)     * 132 + sw4];
            float4 qb1 = *(const float4*)&Q1[(2 * k8p + 1) * 132 + sw4];
#pragma unroll
            for (int ng = 0; ng < 2; ng++) {
                float4 bq[4];
#pragma unroll
                for (int j = 0; j < 4; j++)
                    bq[j] = *(const float4*)&Kf[((ng * 4 + j) * 4 + k8p) * 132 + sw4];
#pragma unroll
                for (int j = 0; j < 4; j++) mma8(S[0][ng*4+j], qa0, bq[j].x, bq[j].y);
#pragma unroll
                for (int j = 0; j < 4; j++) mma8(S[1][ng*4+j], qa1, bq[j].x, bq[j].y);
#pragma unroll
                for (int j = 0; j < 4; j++) mma8(S[0][ng*4+j], qb0, bq[j].z, bq[j].w);
#pragma unroll
                for (int j = 0; j < 4; j++) mma8(S[1][ng*4+j], qb1, bq[j].z, bq[j].w);
            }
        }

        if (more) {
            float* Kn = Kb + (buf ^ 4224);
#pragma unroll
            for (int jj = 0; jj < 8; jj++)
#pragma unroll
                for (int u = 0; u < 4; u++)
                    Kn[koff[u] + jj * 528] = ((const float*)&pk[jj])[u];
        }

        float4 pv4[8];
        if (more) {
#pragma unroll
            for (int jj = 0; jj < 8; jj++)
                pv4[jj] = *(const float4*)&vbase[(size_t)((t+1)*64 + cst + jj*8) * HD + csd];
        }

#pragma unroll
        for (int nt = 0; nt < 8; nt++) {
            S[0][nt].x = ex2(S[0][nt].x); S[0][nt].y = ex2(S[0][nt].y);
            S[0][nt].z = ex2(S[0][nt].z); S[0][nt].w = ex2(S[0][nt].w);
            l0 += S[0][nt].x + S[0][nt].y;
            l1 += S[0][nt].z + S[0][nt].w;
            S[1][nt].x = ex2(S[1][nt].x); S[1][nt].y = ex2(S[1][nt].y);
            S[1][nt].z = ex2(S[1][nt].z); S[1][nt].w = ex2(S[1][nt].w);
            l2 += S[1][nt].x + S[1][nt].y;
            l3 += S[1][nt].z + S[1][nt].w;
        }

        const float* Vf = Vb + buf;
#pragma unroll
        for (int kp = 0; kp < 4; kp++) {
            float4 ape0 = apfrag(S[0][2*kp]);
            float4 apo0 = apfrag(S[0][2*kp+1]);
            float4 ape1 = apfrag(S[1][2*kp]);
            float4 apo1 = apfrag(S[1][2*kp+1]);
#pragma unroll
            for (int ng = 0; ng < 2; ng++) {
                float4 bv[4];
#pragma unroll
                for (int j = 0; j < 4; j++)
                    bv[j] = *(const float4*)&Vf[(kp * 8 + ng * 4 + j) * 132 + sw4];
#pragma unroll
                for (int j = 0; j < 4; j++) mma8(O[0][ng*4+j], ape0, bv[j].x, bv[j].y);
#pragma unroll
                for (int j = 0; j < 4; j++) mma8(O[1][ng*4+j], ape1, bv[j].x, bv[j].y);
#pragma unroll
                for (int j = 0; j < 4; j++) mma8(O[0][ng*4+j], apo0, bv[j].z, bv[j].w);
#pragma unroll
                for (int j = 0; j < 4; j++) mma8(O[1][ng*4+j], apo1, bv[j].z, bv[j].w);
            }
        }

        if (more) {
            float* Vn = Vb + (buf ^ 4224);
#pragma unroll
            for (int jj = 0; jj < 8; jj++)
#pragma unroll
                for (int u = 0; u < 4; u++)
                    Vn[voff[u] + (jj >> 1) * 1056 + (jj & 1) * 2] = ((const float*)&pv4[jj])[u];
        }
        __syncthreads();
    }

    l0 += __shfl_xor_sync(0xffffffffu, l0, 1);
    l0 += __shfl_xor_sync(0xffffffffu, l0, 2);
    l1 += __shfl_xor_sync(0xffffffffu, l1, 1);
    l1 += __shfl_xor_sync(0xffffffffu, l1, 2);
    l2 += __shfl_xor_sync(0xffffffffu, l2, 1);
    l2 += __shfl_xor_sync(0xffffffffu, l2, 2);
    l3 += __shfl_xor_sync(0xffffffffu, l3, 1);
    l3 += __shfl_xor_sync(0xffffffffu, l3, 2);
    float inv_[4] = {1.f / l0, 1.f / l1, 1.f / l2, 1.f / l3};
#pragma unroll
    for (int mt = 0; mt < 2; mt++) {
        int s0 = q0 + (2 * warp + mt) * 16 + g;
        float iv0 = inv_[2 * mt], iv1 = inv_[2 * mt + 1];
#pragma unroll
        for (int nt = 0; nt < 8; nt++) {
            int col = h * HD + nt * 8 + tig * 2;
            *(float2*)&Out[(size_t)(b * SEQL + s0) * EMB + col] =
                make_float2(O[mt][nt].x * iv0, O[mt][nt].y * iv0);
            *(float2*)&Out[(size_t)(b * SEQL + s0 + 8) * EMB + col] =
                make_float2(O[mt][nt].z * iv1, O[mt][nt].w * iv1);
        }
    }
}

// ---------------------------------------------------------------------------
extern "C" void kernel_launch(void* const* d_in, const int* in_sizes, int n_in,
                              void* d_out, int out_size)
{
    const float* x            = (const float*)d_in[0];
    const unsigned char* mask = (const unsigned char*)d_in[1];
    const float* Wqkv         = (const float*)d_in[2];
    const float* Wout         = (const float*)d_in[3];
    float* out = (float*)d_out;

    float *qkv, *q, *k, *v, *attn;
    cudaGetSymbolAddress((void**)&qkv,  g_qkv);
    cudaGetSymbolAddress((void**)&q,    g_q);
    cudaGetSymbolAddress((void**)&k,    g_k);
    cudaGetSymbolAddress((void**)&v,    g_v);
    cudaGetSymbolAddress((void**)&attn, g_attn);

    const int FLASH_SMEM = 27392 * 4;   // 109568 B
    cudaFuncSetAttribute(flash_tf32,
                         cudaFuncAttributeMaxDynamicSharedMemorySize, FLASH_SMEM);

    // keep ncu -s 5 -c 1 window on gemm1 (grid=768)
    dummy_k<<<1, 32>>>();
    dummy_k<<<1, 32>>>();
    dummy_k<<<1, 32>>>();

    dim3 g1(NQKV / 128, M1 / 128);
    gemm_tf32<<<g1, 128>>>(x, Wqkv, qkv, M1, NQKV, EMB);

    split_rope<<<(BATCH*NH*SEQL*32) / 256, 256>>>(qkv, q, k, v);

    dim3 gf(SEQL / 128, NH, BATCH);
    flash_tf32<<<gf, 128, FLASH_SMEM>>>(q, k, v, mask, attn);

    dim3 g2(EMB / 128, M1 / 128);
    gemm_tf32<<<g2, 128>>>(attn, Wout, out, M1, EMB, EMB);
}